// round 1
// baseline (speedup 1.0000x reference)
#include <cuda_runtime.h>
#include <cuda_bf16.h>

#define N_GRID 64
#define N1 65
#define W_FEAT 256

// warp-per-point trilinear gather.
// Each warp: 32 lanes x float4 x 2 iters = 256 feature floats.
__global__ void __launch_bounds__(256) trilerp_kernel(
    const float* __restrict__ x,
    const float* __restrict__ grid_value,
    const float* __restrict__ grid_feature,
    float* __restrict__ out_val,
    float* __restrict__ out_feat,
    int B)
{
    int warp_id = (blockIdx.x * blockDim.x + threadIdx.x) >> 5;
    int lane = threadIdx.x & 31;
    if (warp_id >= B) return;

    // All lanes read the same 3 floats (L1 broadcast).
    float px = x[warp_id * 3 + 0];
    float py = x[warp_id * 3 + 1];
    float pz = x[warp_id * 3 + 2];

    const float min_c = -1.0f;           // -SIDE/2
    const float scale = (float)N_GRID / 2.0f;  // N_GRID / SIDE

    float rx = (px - min_c) * scale;
    float ry = (py - min_c) * scale;
    float rz = (pz - min_c) * scale;

    bool valid = (rx >= 0.0f) && (rx <= (float)N_GRID) &&
                 (ry >= 0.0f) && (ry <= (float)N_GRID) &&
                 (rz >= 0.0f) && (rz <= (float)N_GRID);

    int ix = min(max((int)floorf(rx), 0), N_GRID - 1);
    int iy = min(max((int)floorf(ry), 0), N_GRID - 1);
    int iz = min(max((int)floorf(rz), 0), N_GRID - 1);

    float tx = rx - (float)ix;
    float ty = ry - (float)iy;
    float tz = rz - (float)iz;

    int base = (ix * N1 + iy) * N1 + iz;

    // Corner order matches reference loop (ox,oy,oz).
    float wx0 = 1.0f - tx, wx1 = tx;
    float wy0 = 1.0f - ty, wy1 = ty;
    float wz0 = 1.0f - tz, wz1 = tz;

    int   flat[8];
    float w[8];
    flat[0] = base;                      w[0] = wx0 * wy0 * wz0;
    flat[1] = base + 1;                  w[1] = wx0 * wy0 * wz1;
    flat[2] = base + N1;                 w[2] = wx0 * wy1 * wz0;
    flat[3] = base + N1 + 1;             w[3] = wx0 * wy1 * wz1;
    flat[4] = base + N1 * N1;            w[4] = wx1 * wy0 * wz0;
    flat[5] = base + N1 * N1 + 1;        w[5] = wx1 * wy0 * wz1;
    flat[6] = base + N1 * N1 + N1;       w[6] = wx1 * wy1 * wz0;
    flat[7] = base + N1 * N1 + N1 + 1;   w[7] = wx1 * wy1 * wz1;

    // Feature accumulation: 2 float4 per lane, fully unrolled over 8 corners
    // so all 16 loads are in flight (MLP).
    float4 acc0 = make_float4(0.f, 0.f, 0.f, 0.f);
    float4 acc1 = make_float4(0.f, 0.f, 0.f, 0.f);

    #pragma unroll
    for (int c = 0; c < 8; c++) {
        const float4* row = (const float4*)(grid_feature + (size_t)flat[c] * W_FEAT);
        float4 f0 = __ldg(&row[lane]);
        float4 f1 = __ldg(&row[lane + 32]);
        float wc = w[c];
        acc0.x += wc * f0.x; acc0.y += wc * f0.y;
        acc0.z += wc * f0.z; acc0.w += wc * f0.w;
        acc1.x += wc * f1.x; acc1.y += wc * f1.y;
        acc1.z += wc * f1.z; acc1.w += wc * f1.w;
    }

    if (!valid) {
        acc0 = make_float4(0.f, 0.f, 0.f, 0.f);
        acc1 = make_float4(0.f, 0.f, 0.f, 0.f);
    }

    float4* fo = (float4*)(out_feat + (size_t)warp_id * W_FEAT);
    fo[lane]      = acc0;
    fo[lane + 32] = acc1;

    if (lane == 0) {
        float s = 0.0f;
        #pragma unroll
        for (int c = 0; c < 8; c++) s += w[c] * __ldg(&grid_value[flat[c]]);
        out_val[warp_id] = valid ? s : 0.0f;
    }
}

extern "C" void kernel_launch(void* const* d_in, const int* in_sizes, int n_in,
                              void* d_out, int out_size) {
    const float* x            = (const float*)d_in[0];
    const float* grid_value   = (const float*)d_in[1];
    const float* grid_feature = (const float*)d_in[2];

    int B = in_sizes[0] / 3;

    float* out_val  = (float*)d_out;        // (B, 1)
    float* out_feat = out_val + B;          // (B, 256)

    int warps_per_block = 8;                 // 256 threads
    int blocks = (B + warps_per_block - 1) / warps_per_block;
    trilerp_kernel<<<blocks, 256>>>(x, grid_value, grid_feature,
                                    out_val, out_feat, B);
}

// round 2
// speedup vs baseline: 1.7353x; 1.7353x over previous
#include <cuda_runtime.h>
#include <cuda_bf16.h>

#define N_GRID 64
#define N1 65
#define W_FEAT 256
#define NCELLS (N_GRID * N_GRID * N_GRID)   // 262144
#define B_MAX 262144

// Scratch (allocation-free rule: __device__ globals)
__device__ int g_hist[NCELLS];
__device__ int g_blocksums[256];
__device__ int g_cell[B_MAX];
__device__ int g_perm[B_MAX];

__device__ __forceinline__ void point_cell(const float* __restrict__ x, int p,
                                           int& ix, int& iy, int& iz) {
    const float scale = (float)N_GRID / 2.0f;
    float rx = (x[p * 3 + 0] + 1.0f) * scale;
    float ry = (x[p * 3 + 1] + 1.0f) * scale;
    float rz = (x[p * 3 + 2] + 1.0f) * scale;
    ix = min(max((int)floorf(rx), 0), N_GRID - 1);
    iy = min(max((int)floorf(ry), 0), N_GRID - 1);
    iz = min(max((int)floorf(rz), 0), N_GRID - 1);
}

__global__ void zero_hist_kernel() {
    int i = blockIdx.x * blockDim.x + threadIdx.x;
    if (i < NCELLS) g_hist[i] = 0;
}

__global__ void hist_kernel(const float* __restrict__ x, int B) {
    int p = blockIdx.x * blockDim.x + threadIdx.x;
    if (p >= B) return;
    int ix, iy, iz;
    point_cell(x, p, ix, iy, iz);
    int cell = (ix * N_GRID + iy) * N_GRID + iz;
    g_cell[p] = cell;
    atomicAdd(&g_hist[cell], 1);
}

// 256 blocks x 1024 threads: exclusive scan of each 1024-chunk, block totals out.
__global__ void scan_block_kernel() {
    __shared__ int s[1024];
    int tid = threadIdx.x;
    int i = blockIdx.x * 1024 + tid;
    int v = g_hist[i];
    s[tid] = v;
    __syncthreads();
    #pragma unroll
    for (int off = 1; off < 1024; off <<= 1) {
        int t = (tid >= off) ? s[tid - off] : 0;
        __syncthreads();
        s[tid] += t;
        __syncthreads();
    }
    g_hist[i] = s[tid] - v;           // exclusive
    if (tid == 1023) g_blocksums[blockIdx.x] = s[1023];
}

// 1 block x 256 threads: exclusive scan of block sums.
__global__ void scan_top_kernel() {
    __shared__ int s[256];
    int tid = threadIdx.x;
    int v = g_blocksums[tid];
    s[tid] = v;
    __syncthreads();
    #pragma unroll
    for (int off = 1; off < 256; off <<= 1) {
        int t = (tid >= off) ? s[tid - off] : 0;
        __syncthreads();
        s[tid] += t;
        __syncthreads();
    }
    g_blocksums[tid] = s[tid] - v;    // exclusive
}

__global__ void scan_add_kernel() {
    int i = blockIdx.x * blockDim.x + threadIdx.x;
    if (i < NCELLS) g_hist[i] += g_blocksums[i >> 10];
}

__global__ void scatter_kernel(int B) {
    int p = blockIdx.x * blockDim.x + threadIdx.x;
    if (p >= B) return;
    int pos = atomicAdd(&g_hist[g_cell[p]], 1);
    g_perm[pos] = p;
}

// warp-per-point trilinear gather; warps walk points in cell-sorted order.
__global__ void __launch_bounds__(256) trilerp_kernel(
    const float* __restrict__ x,
    const float* __restrict__ grid_value,
    const float* __restrict__ grid_feature,
    float* __restrict__ out_val,
    float* __restrict__ out_feat,
    int B)
{
    int warp_id = (blockIdx.x * blockDim.x + threadIdx.x) >> 5;
    int lane = threadIdx.x & 31;
    if (warp_id >= B) return;

    int p = g_perm[warp_id];

    float px = x[p * 3 + 0];
    float py = x[p * 3 + 1];
    float pz = x[p * 3 + 2];

    const float scale = (float)N_GRID / 2.0f;
    float rx = (px + 1.0f) * scale;
    float ry = (py + 1.0f) * scale;
    float rz = (pz + 1.0f) * scale;

    bool valid = (rx >= 0.0f) && (rx <= (float)N_GRID) &&
                 (ry >= 0.0f) && (ry <= (float)N_GRID) &&
                 (rz >= 0.0f) && (rz <= (float)N_GRID);

    int ix = min(max((int)floorf(rx), 0), N_GRID - 1);
    int iy = min(max((int)floorf(ry), 0), N_GRID - 1);
    int iz = min(max((int)floorf(rz), 0), N_GRID - 1);

    float tx = rx - (float)ix;
    float ty = ry - (float)iy;
    float tz = rz - (float)iz;

    int base = (ix * N1 + iy) * N1 + iz;

    float wx0 = 1.0f - tx, wx1 = tx;
    float wy0 = 1.0f - ty, wy1 = ty;
    float wz0 = 1.0f - tz, wz1 = tz;

    int   flat[8];
    float w[8];
    flat[0] = base;                      w[0] = wx0 * wy0 * wz0;
    flat[1] = base + 1;                  w[1] = wx0 * wy0 * wz1;
    flat[2] = base + N1;                 w[2] = wx0 * wy1 * wz0;
    flat[3] = base + N1 + 1;             w[3] = wx0 * wy1 * wz1;
    flat[4] = base + N1 * N1;            w[4] = wx1 * wy0 * wz0;
    flat[5] = base + N1 * N1 + 1;        w[5] = wx1 * wy0 * wz1;
    flat[6] = base + N1 * N1 + N1;       w[6] = wx1 * wy1 * wz0;
    flat[7] = base + N1 * N1 + N1 + 1;   w[7] = wx1 * wy1 * wz1;

    float4 acc0 = make_float4(0.f, 0.f, 0.f, 0.f);
    float4 acc1 = make_float4(0.f, 0.f, 0.f, 0.f);

    #pragma unroll
    for (int c = 0; c < 8; c++) {
        const float4* row = (const float4*)(grid_feature + (size_t)flat[c] * W_FEAT);
        float4 f0 = __ldg(&row[lane]);
        float4 f1 = __ldg(&row[lane + 32]);
        float wc = w[c];
        acc0.x += wc * f0.x; acc0.y += wc * f0.y;
        acc0.z += wc * f0.z; acc0.w += wc * f0.w;
        acc1.x += wc * f1.x; acc1.y += wc * f1.y;
        acc1.z += wc * f1.z; acc1.w += wc * f1.w;
    }

    if (!valid) {
        acc0 = make_float4(0.f, 0.f, 0.f, 0.f);
        acc1 = make_float4(0.f, 0.f, 0.f, 0.f);
    }

    float4* fo = (float4*)(out_feat + (size_t)p * W_FEAT);
    fo[lane]      = acc0;
    fo[lane + 32] = acc1;

    if (lane == 0) {
        float s = 0.0f;
        #pragma unroll
        for (int c = 0; c < 8; c++) s += w[c] * __ldg(&grid_value[flat[c]]);
        out_val[p] = valid ? s : 0.0f;
    }
}

extern "C" void kernel_launch(void* const* d_in, const int* in_sizes, int n_in,
                              void* d_out, int out_size) {
    const float* x            = (const float*)d_in[0];
    const float* grid_value   = (const float*)d_in[1];
    const float* grid_feature = (const float*)d_in[2];

    int B = in_sizes[0] / 3;

    float* out_val  = (float*)d_out;        // (B, 1)
    float* out_feat = out_val + B;          // (B, 256)

    // --- counting sort by cell id ---
    zero_hist_kernel<<<(NCELLS + 255) / 256, 256>>>();
    hist_kernel<<<(B + 255) / 256, 256>>>(x, B);
    scan_block_kernel<<<NCELLS / 1024, 1024>>>();
    scan_top_kernel<<<1, 256>>>();
    scan_add_kernel<<<(NCELLS + 255) / 256, 256>>>();
    scatter_kernel<<<(B + 255) / 256, 256>>>(B);

    // --- main gather in sorted order ---
    int warps_per_block = 8;                 // 256 threads
    int blocks = (B + warps_per_block - 1) / warps_per_block;
    trilerp_kernel<<<blocks, 256>>>(x, grid_value, grid_feature,
                                    out_val, out_feat, B);
}